// round 16
// baseline (speedup 1.0000x reference)
#include <cuda_runtime.h>
#include <cuda_fp16.h>
#include <cstdint>

// SpiralConv gather-GEMM. R16 = R14 + fp16-accumulate MMA (m16n8k16 f16.f16.f16.f16,
// presumed rt=4 vs 8 for f32-accum) with per-32K-group promotion into fp32 masters.
// out[m,o] = relu(sum_k A[m,k]*W[o,k] + b[o]) * zp[m%N]; M=96000, K=2048, N=128.

constexpr int Bq = 8, Nq = 12000, Fq = 128, Sq = 16, OUTq = 128;
constexpr int Kq = Sq * Fq;       // 2048
constexpr int Mtot = Bq * Nq;     // 96000
constexpr int BM = 128;
constexpr int NITER = Kq / 64;    // 32 (BK=64)
constexpr int NST = 3;

__device__ __half g_x[Bq * Nq * Fq];
__device__ __half g_w[OUTq * Kq];

constexpr int STG = BM * 128;                       // 16384 per tile stage
constexpr int OFF_A = 0;
constexpr int OFF_B = OFF_A + NST * STG;            // 49152
constexpr int OFF_ATAB = OFF_B + NST * STG;         // 98304
constexpr int OFF_BIAS = OFF_ATAB + BM * Sq * 4;    // 106496
constexpr int OFF_MBAR = OFF_BIAS + OUTq * 4;       // 107008
constexpr int SMEM_BYTES = OFF_MBAR + NST * 16;     // 107056

__device__ __forceinline__ void cp_async16(void* sdst, const void* gsrc) {
    unsigned d = (unsigned)__cvta_generic_to_shared(sdst);
    asm volatile("cp.async.cg.shared.global [%0], [%1], 16;" :: "r"(d), "l"(gsrc));
}

__device__ __forceinline__ void mbar_init(uint32_t a, uint32_t cnt) {
    asm volatile("mbarrier.init.shared.b64 [%0], %1;" :: "r"(a), "r"(cnt) : "memory");
}
__device__ __forceinline__ void mbar_arrive(uint32_t a) {
    asm volatile("mbarrier.arrive.shared::cta.b64 _, [%0];" :: "r"(a) : "memory");
}
__device__ __forceinline__ void cpasync_mbar_arrive_noinc(uint32_t a) {
    asm volatile("cp.async.mbarrier.arrive.noinc.shared::cta.b64 [%0];" :: "r"(a) : "memory");
}
__device__ __forceinline__ void mbar_wait(uint32_t a, uint32_t parity) {
    uint32_t done;
    asm volatile("{\n\t.reg .pred p;\n\t"
                 "mbarrier.try_wait.parity.acquire.cta.shared::cta.b64 p, [%1], %2;\n\t"
                 "selp.b32 %0, 1, 0, p;\n\t}"
                 : "=r"(done) : "r"(a), "r"(parity) : "memory");
    if (!done) {
        asm volatile("{\n\t.reg .pred P1;\n\t"
                     "W_%=:\n\t"
                     "mbarrier.try_wait.parity.acquire.cta.shared::cta.b64 P1, [%0], %1, 0x989680;\n\t"
                     "@P1 bra.uni D_%=;\n\t"
                     "bra.uni W_%=;\n\t"
                     "D_%=:\n\t}"
                     :: "r"(a), "r"(parity) : "memory");
    }
}
__device__ __forceinline__ void mbar_wait_relaxed(uint32_t a, uint32_t parity) {
    uint32_t done;
    asm volatile("{\n\t.reg .pred p;\n\t"
                 "mbarrier.try_wait.parity.relaxed.cta.shared::cta.b64 p, [%1], %2;\n\t"
                 "selp.b32 %0, 1, 0, p;\n\t}"
                 : "=r"(done) : "r"(a), "r"(parity) : "memory");
    if (!done) {
        asm volatile("{\n\t.reg .pred P1;\n\t"
                     "W_%=:\n\t"
                     "mbarrier.try_wait.parity.relaxed.cta.shared::cta.b64 P1, [%0], %1, 0x989680;\n\t"
                     "@P1 bra.uni D_%=;\n\t"
                     "bra.uni W_%=;\n\t"
                     "D_%=:\n\t}"
                     :: "r"(a), "r"(parity) : "memory");
    }
}

#define LDS128I(v, addr, IMM) \
    asm volatile("ld.shared.v4.u32 {%0,%1,%2,%3}, [%4+%5];" \
        : "=r"((v).x), "=r"((v).y), "=r"((v).z), "=r"((v).w) \
        : "r"(addr), "n"(IMM))

// fp16-accumulate MMAs: INIT uses C = {0,0} (zero register), ACC chains D=C.
#define MMAH_INIT(D0, D1, A0, A1, A2, A3, B0, B1) \
    asm volatile("mma.sync.aligned.m16n8k16.row.col.f16.f16.f16.f16 " \
        "{%0,%1}, {%2,%3,%4,%5}, {%6,%7}, {%8,%8};" \
        : "=r"(D0), "=r"(D1) \
        : "r"(A0), "r"(A1), "r"(A2), "r"(A3), "r"(B0), "r"(B1), "r"(0u))

#define MMAH_ACC(D0, D1, A0, A1, A2, A3, B0, B1) \
    asm volatile("mma.sync.aligned.m16n8k16.row.col.f16.f16.f16.f16 " \
        "{%0,%1}, {%2,%3,%4,%5}, {%6,%7}, {%0,%1};" \
        : "+r"(D0), "+r"(D1) \
        : "r"(A0), "r"(A1), "r"(A2), "r"(A3), "r"(B0), "r"(B1))

#define PROMO(MT, NT, D0, D1) { \
    float2 f0 = __half22float2(*reinterpret_cast<__half2*>(&(D0))); \
    float2 f1 = __half22float2(*reinterpret_cast<__half2*>(&(D1))); \
    acc[MT][NT][0] += f0.x; acc[MT][NT][1] += f0.y; \
    acc[MT][NT][2] += f1.x; acc[MT][NT][3] += f1.y; }

// ---- prepass: fp32 -> fp16 with per-32-group fragment permutation ----
__global__ void prep_kernel(const float* __restrict__ x, const float* __restrict__ W,
                            int xch, int totch) {
    int t = blockIdx.x * 256 + threadIdx.x;
    if (t >= totch) return;
    const float* src;
    __half* dst;
    int ch = t;
    if (t < xch) { src = x; dst = g_x; }
    else         { src = W; dst = g_w; ch = t - xch; }
    int gb = (ch >> 2) * 32 + (ch & 3) * 2;
    __half2 h0 = __float22half2_rn(*reinterpret_cast<const float2*>(src + gb));
    __half2 h1 = __float22half2_rn(*reinterpret_cast<const float2*>(src + gb + 8));
    __half2 h2 = __float22half2_rn(*reinterpret_cast<const float2*>(src + gb + 16));
    __half2 h3 = __float22half2_rn(*reinterpret_cast<const float2*>(src + gb + 24));
    uint4 v;
    v.x = *reinterpret_cast<uint32_t*>(&h0);
    v.y = *reinterpret_cast<uint32_t*>(&h1);
    v.z = *reinterpret_cast<uint32_t*>(&h2);
    v.w = *reinterpret_cast<uint32_t*>(&h3);
    reinterpret_cast<uint4*>(dst)[ch] = v;
}

extern __shared__ char smem[];

__global__ __launch_bounds__(256, 2) void spiral_mma_kernel(
    const float* __restrict__ bias,
    const int*   __restrict__ adj,
    const float* __restrict__ zp,
    float*       __restrict__ out)
{
    const int tid = threadIdx.x;
    const int m0 = blockIdx.x * BM;
    uint32_t sb;
    asm("{ .reg .u64 t; cvta.to.shared.u64 t, %1; cvt.u32.u64 %0, t; }"
        : "=r"(sb) : "l"(smem));

    uint32_t* atab  = reinterpret_cast<uint32_t*>(smem + OFF_ATAB);
    float*    sbias = reinterpret_cast<float*>(smem + OFF_BIAS);

    for (int i = tid; i < BM * Sq; i += 256) {
        int r = i >> 4, s = i & 15;
        int mm = m0 + r;
        int b = mm / Nq, n = mm - b * Nq;
        atab[i] = (uint32_t)(b * Nq + adj[n * Sq + s]) << 8;
    }
    if (tid < OUTq) sbias[tid] = bias[tid];
    if (tid == 0) {
        #pragma unroll
        for (int s = 0; s < NST; ++s) {
            mbar_init(sb + OFF_MBAR + s * 16, 256);      // full[s]
            mbar_init(sb + OFF_MBAR + s * 16 + 8, 256);  // empty[s]
        }
    }
    __syncthreads();

    // loader: 8 lanes per 128B row; rows lr+32j
    const int lr = tid >> 3;
    const int lc = tid & 7;
    const int gsl = lc >> 2;
    const int csl = lc & 3;
    const uint32_t* atp = atab + lr * 16;
    int adst[4];
    const char* wsrc[4];
    #pragma unroll
    for (int j = 0; j < 4; ++j) {
        int row = lr + j * 32;
        int pos = ((gsl ^ (row & 1)) << 2) + (csl ^ ((row >> 1) & 3));
        adst[j] = row * 128 + (pos << 4);
        wsrc[j] = reinterpret_cast<const char*>(g_w) + row * (Kq * 2) + lc * 16;
    }

    auto produce = [&](int st, int parity, int it2) {
        mbar_wait_relaxed(sb + OFF_MBAR + st * 16 + 8, parity);   // empty[st]
        const int sidx = it2 >> 1;
        const char* gx = reinterpret_cast<const char*>(g_x)
                       + ((it2 & 1) << 7) + lc * 16;
        const int wadv = it2 << 7;
        char* abase = smem + OFF_A + st * STG;
        char* bbase = smem + OFF_B + st * STG;
        #pragma unroll
        for (int j = 0; j < 4; ++j)
            cp_async16(abase + adst[j], gx + atp[512 * j + sidx]);
        #pragma unroll
        for (int j = 0; j < 4; ++j)
            cp_async16(bbase + adst[j], wsrc[j] + wadv);
        cpasync_mbar_arrive_noinc(sb + OFF_MBAR + st * 16);       // full[st]
    };

    const int lane = tid & 31;
    const int warp = tid >> 5;
    const int wm = (warp & 1) * 64;   // 2 warps over M
    const int wn = (warp >> 1) * 32;  // 4 warps over N
    const int tr = lane >> 2;
    const int tc = lane & 3;
    const int par = tr & 1;
    const int q2  = tr >> 1;
    const int chn0 = ((0 ^ par) << 2) + (tc ^ q2);
    const int chn1 = ((1 ^ par) << 2) + (tc ^ q2);

    const uint32_t abase0 = sb + OFF_A + (wm + tr) * 128 + chn0 * 16;
    const uint32_t abase1 = sb + OFF_A + (wm + tr) * 128 + chn1 * 16;
    const uint32_t bbase0 = sb + OFF_B + (wn + tr) * 128 + chn0 * 16;
    const uint32_t bbase1 = sb + OFF_B + (wn + tr) * 128 + chn1 * 16;

    float acc[4][4][4];
    #pragma unroll
    for (int a = 0; a < 4; ++a)
        #pragma unroll
        for (int b2 = 0; b2 < 4; ++b2)
            #pragma unroll
            for (int cc = 0; cc < 4; ++cc) acc[a][b2][cc] = 0.f;

// one mt-block: fp16-acc MMAs for 4 nt tiles (both k-steps), then promote to fp32
#define MT_BLOCK_H(MT, AB)                                                    \
    {                                                                         \
        uint4 alo, ahi;                                                       \
        LDS128I(alo, (AB), (MT)*2048);                                        \
        LDS128I(ahi, (AB), (MT)*2048 + 1024);                                 \
        uint32_t d00, d01, d10, d11, d20, d21, d30, d31;                      \
        MMAH_INIT(d00, d01, alo.x, ahi.x, alo.y, ahi.y, bf0.x, bf0.y);        \
        MMAH_INIT(d10, d11, alo.x, ahi.x, alo.y, ahi.y, bf1.x, bf1.y);        \
        MMAH_INIT(d20, d21, alo.x, ahi.x, alo.y, ahi.y, bf2.x, bf2.y);        \
        MMAH_INIT(d30, d31, alo.x, ahi.x, alo.y, ahi.y, bf3.x, bf3.y);        \
        MMAH_ACC(d00, d01, alo.z, ahi.z, alo.w, ahi.w, bf0.z, bf0.w);         \
        MMAH_ACC(d10, d11, alo.z, ahi.z, alo.w, ahi.w, bf1.z, bf1.w);         \
        MMAH_ACC(d20, d21, alo.z, ahi.z, alo.w, ahi.w, bf2.z, bf2.w);         \
        MMAH_ACC(d30, d31, alo.z, ahi.z, alo.w, ahi.w, bf3.z, bf3.w);         \
        PROMO(MT, 0, d00, d01) PROMO(MT, 1, d10, d11)                         \
        PROMO(MT, 2, d20, d21) PROMO(MT, 3, d30, d31)                         \
    }

#define CONSUME_G(AB, BB)                                                     \
    {                                                                         \
        uint4 bf0, bf1, bf2, bf3;                                             \
        LDS128I(bf0, (BB), 0);                                                \
        LDS128I(bf1, (BB), 1024);                                             \
        LDS128I(bf2, (BB), 2048);                                             \
        LDS128I(bf3, (BB), 3072);                                             \
        MT_BLOCK_H(0, AB) MT_BLOCK_H(1, AB)                                   \
        MT_BLOCK_H(2, AB) MT_BLOCK_H(3, AB)                                   \
    }

    // prologue (fresh-barrier empty-waits pass with parity 1)
    produce(0, 1, 0);
    produce(1, 1, 1);

    int ps = 2, pp = 1;
    int cs = 0, cp = 0;
    #pragma unroll 1
    for (int it = 0; it < NITER; ++it) {
        mbar_wait(sb + OFF_MBAR + cs * 16, cp);         // full[cs]
        const uint32_t co = (uint32_t)(cs * STG);
        const uint32_t ab0 = abase0 + co, ab1 = abase1 + co;
        const uint32_t bb0 = bbase0 + co, bb1 = bbase1 + co;

        CONSUME_G(ab0, bb0)                              // group 0

        if (it + 2 < NITER) {
            produce(ps, pp, it + 2);
            if (++ps == NST) { ps = 0; pp ^= 1; }
        }

        CONSUME_G(ab1, bb1)                              // group 1

        mbar_arrive(sb + OFF_MBAR + cs * 16 + 8);        // empty[cs]
        if (++cs == NST) { cs = 0; cp ^= 1; }
    }

    // ---- epilogue: bias + relu + zero_padding ----
    #pragma unroll
    for (int mt = 0; mt < 4; ++mt) {
        #pragma unroll
        for (int hh = 0; hh < 2; ++hh) {
            int m = m0 + wm + mt * 16 + hh * 8 + tr;
            float z = zp[m % Nq];
            float* orow = out + (long)m * OUTq;
            #pragma unroll
            for (int nt = 0; nt < 4; ++nt) {
                int o = wn + nt * 8 + 2 * tc;
                float v0 = fmaxf(acc[mt][nt][hh * 2 + 0] + sbias[o], 0.f) * z;
                float v1 = fmaxf(acc[mt][nt][hh * 2 + 1] + sbias[o + 1], 0.f) * z;
                *reinterpret_cast<float2*>(orow + o) = make_float2(v0, v1);
            }
        }
    }
}

extern "C" void kernel_launch(void* const* d_in, const int* in_sizes, int n_in,
                              void* d_out, int out_size) {
    const float* x    = (const float*)d_in[0];
    const float* W    = (const float*)d_in[1];
    const float* bias = (const float*)d_in[2];
    const int*   adj  = (const int*)d_in[3];
    const float* zp   = (const float*)d_in[4];
    float* out = (float*)d_out;

    int xch = (Bq * Nq * Fq) / 8;
    int totch = xch + (OUTq * Kq) / 8;
    prep_kernel<<<(totch + 255) / 256, 256>>>(x, W, xch, totch);

    cudaFuncSetAttribute(spiral_mma_kernel,
                         cudaFuncAttributeMaxDynamicSharedMemorySize, SMEM_BYTES);
    spiral_mma_kernel<<<Mtot / BM, 256, SMEM_BYTES>>>(bias, adj, zp, out);
}

// round 17
// speedup vs baseline: 1.2712x; 1.2712x over previous
#include <cuda_runtime.h>
#include <cuda_fp16.h>
#include <cstdint>

// SpiralConv gather-GEMM. R17 = R14 (FP16 m16n8k16 f32-acc, BK=64, mbar
// free-run) + register slimming (collapsed loader addressing, shared-space
// cp.async) + explicit one-MT-ahead fragment prefetch rotation.
// out[m,o] = relu(sum_k A[m,k]*W[o,k] + b[o]) * zp[m%N]; M=96000, K=2048, N=128.

constexpr int Bq = 8, Nq = 12000, Fq = 128, Sq = 16, OUTq = 128;
constexpr int Kq = Sq * Fq;       // 2048
constexpr int Mtot = Bq * Nq;     // 96000
constexpr int BM = 128;
constexpr int NITER = Kq / 64;    // 32 (BK=64)
constexpr int NST = 3;

__device__ __half g_x[Bq * Nq * Fq];
__device__ __half g_w[OUTq * Kq];

constexpr int STG = BM * 128;                       // 16384 per tile stage
constexpr int OFF_A = 0;
constexpr int OFF_B = OFF_A + NST * STG;            // 49152
constexpr int OFF_ATAB = OFF_B + NST * STG;         // 98304
constexpr int OFF_BIAS = OFF_ATAB + BM * Sq * 4;    // 106496
constexpr int OFF_MBAR = OFF_BIAS + OUTq * 4;       // 107008
constexpr int SMEM_BYTES = OFF_MBAR + NST * 16;     // 107056

__device__ __forceinline__ void cp_async16s(uint32_t sdst, const void* gsrc) {
    asm volatile("cp.async.cg.shared.global [%0], [%1], 16;" :: "r"(sdst), "l"(gsrc));
}

__device__ __forceinline__ void mbar_init(uint32_t a, uint32_t cnt) {
    asm volatile("mbarrier.init.shared.b64 [%0], %1;" :: "r"(a), "r"(cnt) : "memory");
}
__device__ __forceinline__ void mbar_arrive(uint32_t a) {
    asm volatile("mbarrier.arrive.shared::cta.b64 _, [%0];" :: "r"(a) : "memory");
}
__device__ __forceinline__ void cpasync_mbar_arrive_noinc(uint32_t a) {
    asm volatile("cp.async.mbarrier.arrive.noinc.shared::cta.b64 [%0];" :: "r"(a) : "memory");
}
__device__ __forceinline__ void mbar_wait(uint32_t a, uint32_t parity) {
    uint32_t done;
    asm volatile("{\n\t.reg .pred p;\n\t"
                 "mbarrier.try_wait.parity.acquire.cta.shared::cta.b64 p, [%1], %2;\n\t"
                 "selp.b32 %0, 1, 0, p;\n\t}"
                 : "=r"(done) : "r"(a), "r"(parity) : "memory");
    if (!done) {
        asm volatile("{\n\t.reg .pred P1;\n\t"
                     "W_%=:\n\t"
                     "mbarrier.try_wait.parity.acquire.cta.shared::cta.b64 P1, [%0], %1, 0x989680;\n\t"
                     "@P1 bra.uni D_%=;\n\t"
                     "bra.uni W_%=;\n\t"
                     "D_%=:\n\t}"
                     :: "r"(a), "r"(parity) : "memory");
    }
}
__device__ __forceinline__ void mbar_wait_relaxed(uint32_t a, uint32_t parity) {
    uint32_t done;
    asm volatile("{\n\t.reg .pred p;\n\t"
                 "mbarrier.try_wait.parity.relaxed.cta.shared::cta.b64 p, [%1], %2;\n\t"
                 "selp.b32 %0, 1, 0, p;\n\t}"
                 : "=r"(done) : "r"(a), "r"(parity) : "memory");
    if (!done) {
        asm volatile("{\n\t.reg .pred P1;\n\t"
                     "W_%=:\n\t"
                     "mbarrier.try_wait.parity.relaxed.cta.shared::cta.b64 P1, [%0], %1, 0x989680;\n\t"
                     "@P1 bra.uni D_%=;\n\t"
                     "bra.uni W_%=;\n\t"
                     "D_%=:\n\t}"
                     :: "r"(a), "r"(parity) : "memory");
    }
}

#define LDS128I(v, addr, IMM) \
    asm volatile("ld.shared.v4.u32 {%0,%1,%2,%3}, [%4+%5];" \
        : "=r"((v).x), "=r"((v).y), "=r"((v).z), "=r"((v).w) \
        : "r"(addr), "n"(IMM))

#define MMA16816(acc4, A0, A1, A2, A3, B0, B1) \
    asm volatile("mma.sync.aligned.m16n8k16.row.col.f32.f16.f16.f32 " \
        "{%0,%1,%2,%3}, {%4,%5,%6,%7}, {%8,%9}, {%0,%1,%2,%3};" \
        : "+f"((acc4)[0]), "+f"((acc4)[1]), "+f"((acc4)[2]), "+f"((acc4)[3]) \
        : "r"(A0), "r"(A1), "r"(A2), "r"(A3), "r"(B0), "r"(B1))

// ---- prepass: fp32 -> fp16 with per-32-group fragment permutation ----
__global__ void prep_kernel(const float* __restrict__ x, const float* __restrict__ W,
                            int xch, int totch) {
    int t = blockIdx.x * 256 + threadIdx.x;
    if (t >= totch) return;
    const float* src;
    __half* dst;
    int ch = t;
    if (t < xch) { src = x; dst = g_x; }
    else         { src = W; dst = g_w; ch = t - xch; }
    int gb = (ch >> 2) * 32 + (ch & 3) * 2;
    __half2 h0 = __float22half2_rn(*reinterpret_cast<const float2*>(src + gb));
    __half2 h1 = __float22half2_rn(*reinterpret_cast<const float2*>(src + gb + 8));
    __half2 h2 = __float22half2_rn(*reinterpret_cast<const float2*>(src + gb + 16));
    __half2 h3 = __float22half2_rn(*reinterpret_cast<const float2*>(src + gb + 24));
    uint4 v;
    v.x = *reinterpret_cast<uint32_t*>(&h0);
    v.y = *reinterpret_cast<uint32_t*>(&h1);
    v.z = *reinterpret_cast<uint32_t*>(&h2);
    v.w = *reinterpret_cast<uint32_t*>(&h3);
    reinterpret_cast<uint4*>(dst)[ch] = v;
}

extern __shared__ char smem[];

__global__ __launch_bounds__(256, 2) void spiral_mma_kernel(
    const float* __restrict__ bias,
    const int*   __restrict__ adj,
    const float* __restrict__ zp,
    float*       __restrict__ out)
{
    const int tid = threadIdx.x;
    const int m0 = blockIdx.x * BM;
    uint32_t sb;
    asm("{ .reg .u64 t; cvta.to.shared.u64 t, %1; cvt.u32.u64 %0, t; }"
        : "=r"(sb) : "l"(smem));

    uint32_t* atab  = reinterpret_cast<uint32_t*>(smem + OFF_ATAB);
    float*    sbias = reinterpret_cast<float*>(smem + OFF_BIAS);

    for (int i = tid; i < BM * Sq; i += 256) {
        int r = i >> 4, s = i & 15;
        int mm = m0 + r;
        int b = mm / Nq, n = mm - b * Nq;
        atab[i] = (uint32_t)(b * Nq + adj[n * Sq + s]) << 8;
    }
    if (tid < OUTq) sbias[tid] = bias[tid];
    if (tid == 0) {
        #pragma unroll
        for (int s = 0; s < NST; ++s) {
            mbar_init(sb + OFF_MBAR + s * 16, 256);      // full[s]
            mbar_init(sb + OFF_MBAR + s * 16 + 8, 256);  // empty[s]
        }
    }
    __syncthreads();

    // loader: 8 lanes per 128B row; rows lr+32j. Since rows differ by 32, the
    // chunk swizzle is identical for all j -> dsts = adst0 + j*4096.
    const int lr = tid >> 3;
    const int lc = tid & 7;
    const int pos0 = (((lc >> 2) ^ (lr & 1)) << 2) + ((lc & 3) ^ ((lr >> 1) & 3));
    const uint32_t adst0 = (uint32_t)(lr * 128 + (pos0 << 4));
    const uint32_t* atp = atab + lr * 16;            // [512*j + sidx]
    const char* wbase = reinterpret_cast<const char*>(g_w) + lr * (Kq * 2) + lc * 16;
    const char* gxb   = reinterpret_cast<const char*>(g_x) + lc * 16;

    auto produce = [&](int st, int parity, int it2) {
        mbar_wait_relaxed(sb + OFF_MBAR + st * 16 + 8, parity);   // empty[st]
        const int sidx = it2 >> 1;
        const char* gx = gxb + ((it2 & 1) << 7);
        const char* gw = wbase + (it2 << 7);
        const uint32_t ad = sb + OFF_A + st * STG + adst0;
        const uint32_t bd = sb + OFF_B + st * STG + adst0;
        #pragma unroll
        for (int j = 0; j < 4; ++j)
            cp_async16s(ad + j * 4096, gx + atp[512 * j + sidx]);
        #pragma unroll
        for (int j = 0; j < 4; ++j)
            cp_async16s(bd + j * 4096, gw + j * 131072);
        cpasync_mbar_arrive_noinc(sb + OFF_MBAR + st * 16);       // full[st]
    };

    const int lane = tid & 31;
    const int warp = tid >> 5;
    const int wm = (warp & 1) * 64;   // 2 warps over M
    const int wn = (warp >> 1) * 32;  // 4 warps over N
    const int tr = lane >> 2;
    const int tc = lane & 3;
    const int par = tr & 1;
    const int q2  = tr >> 1;
    const int chn0 = ((0 ^ par) << 2) + (tc ^ q2);
    const int chn1 = ((1 ^ par) << 2) + (tc ^ q2);

    const uint32_t abase0 = sb + OFF_A + (wm + tr) * 128 + chn0 * 16;
    const uint32_t abase1 = sb + OFF_A + (wm + tr) * 128 + chn1 * 16;
    const uint32_t bbase0 = sb + OFF_B + (wn + tr) * 128 + chn0 * 16;
    const uint32_t bbase1 = sb + OFF_B + (wn + tr) * 128 + chn1 * 16;

    float acc[4][4][4];
    #pragma unroll
    for (int a = 0; a < 4; ++a)
        #pragma unroll
        for (int b2 = 0; b2 < 4; ++b2)
            #pragma unroll
            for (int cc = 0; cc < 4; ++cc) acc[a][b2][cc] = 0.f;

    // 8 MMAs for one MT block given its A-pair (L, H) and the 4 B frags
#define MMA8(MT, L, H)                                                        \
    MMA16816(acc[MT][0], (L).x, (H).x, (L).y, (H).y, bf0.x, bf0.y);           \
    MMA16816(acc[MT][1], (L).x, (H).x, (L).y, (H).y, bf1.x, bf1.y);           \
    MMA16816(acc[MT][2], (L).x, (H).x, (L).y, (H).y, bf2.x, bf2.y);           \
    MMA16816(acc[MT][3], (L).x, (H).x, (L).y, (H).y, bf3.x, bf3.y);           \
    MMA16816(acc[MT][0], (L).z, (H).z, (L).w, (H).w, bf0.z, bf0.w);           \
    MMA16816(acc[MT][1], (L).z, (H).z, (L).w, (H).w, bf1.z, bf1.w);           \
    MMA16816(acc[MT][2], (L).z, (H).z, (L).w, (H).w, bf2.z, bf2.w);           \
    MMA16816(acc[MT][3], (L).z, (H).z, (L).w, (H).w, bf3.z, bf3.w);

    // one g-group, rotated: MMA(mt) overlaps LDS(mt+2)
    auto consume_g = [&](uint32_t ab, uint32_t bb) {
        uint4 bf0, bf1, bf2, bf3, pA, pB, qA, qB;
        LDS128I(bf0, bb, 0);
        LDS128I(bf1, bb, 1024);
        LDS128I(bf2, bb, 2048);
        LDS128I(bf3, bb, 3072);
        LDS128I(pA, ab, 0);      LDS128I(pB, ab, 1024);   // mt0
        LDS128I(qA, ab, 2048);   LDS128I(qB, ab, 3072);   // mt1
        MMA8(0, pA, pB)
        LDS128I(pA, ab, 4096);   LDS128I(pB, ab, 5120);   // mt2
        MMA8(1, qA, qB)
        LDS128I(qA, ab, 6144);   LDS128I(qB, ab, 7168);   // mt3
        MMA8(2, pA, pB)
        MMA8(3, qA, qB)
    };

    // prologue (fresh-barrier empty-waits pass with parity 1)
    produce(0, 1, 0);
    produce(1, 1, 1);

    int ps = 2, pp = 1;
    int cs = 0, cp = 0;
    #pragma unroll 1
    for (int it = 0; it < NITER; ++it) {
        mbar_wait(sb + OFF_MBAR + cs * 16, cp);         // full[cs]
        const uint32_t co = (uint32_t)(cs * STG);

        consume_g(abase0 + co, bbase0 + co);             // group 0

        if (it + 2 < NITER) {
            produce(ps, pp, it + 2);
            if (++ps == NST) { ps = 0; pp ^= 1; }
        }

        consume_g(abase1 + co, bbase1 + co);             // group 1

        mbar_arrive(sb + OFF_MBAR + cs * 16 + 8);        // empty[cs]
        if (++cs == NST) { cs = 0; cp ^= 1; }
    }

    // ---- epilogue: bias + relu + zero_padding ----
    #pragma unroll
    for (int mt = 0; mt < 4; ++mt) {
        #pragma unroll
        for (int hh = 0; hh < 2; ++hh) {
            int m = m0 + wm + mt * 16 + hh * 8 + tr;
            float z = zp[m % Nq];
            float* orow = out + (long)m * OUTq;
            #pragma unroll
            for (int nt = 0; nt < 4; ++nt) {
                int o = wn + nt * 8 + 2 * tc;
                float v0 = fmaxf(acc[mt][nt][hh * 2 + 0] + sbias[o], 0.f) * z;
                float v1 = fmaxf(acc[mt][nt][hh * 2 + 1] + sbias[o + 1], 0.f) * z;
                *reinterpret_cast<float2*>(orow + o) = make_float2(v0, v1);
            }
        }
    }
}

extern "C" void kernel_launch(void* const* d_in, const int* in_sizes, int n_in,
                              void* d_out, int out_size) {
    const float* x    = (const float*)d_in[0];
    const float* W    = (const float*)d_in[1];
    const float* bias = (const float*)d_in[2];
    const int*   adj  = (const int*)d_in[3];
    const float* zp   = (const float*)d_in[4];
    float* out = (float*)d_out;

    int xch = (Bq * Nq * Fq) / 8;
    int totch = xch + (OUTq * Kq) / 8;
    prep_kernel<<<(totch + 255) / 256, 256>>>(x, W, xch, totch);

    cudaFuncSetAttribute(spiral_mma_kernel,
                         cudaFuncAttributeMaxDynamicSharedMemorySize, SMEM_BYTES);
    spiral_mma_kernel<<<Mtot / BM, 256, SMEM_BYTES>>>(bias, adj, zp, out);
}